// round 1
// baseline (speedup 1.0000x reference)
#include <cuda_runtime.h>
#include <math.h>

#define SEQL 4096
#define BATCH 2
#define DMODEL 256
#define DINNER 512
#define NSTATE 16
#define DTRANK 16
#define M_TOT (BATCH*SEQL)   // 8192

// -------- scratch (device globals; no dynamic allocation) --------
__device__ float g_xz[(size_t)M_TOT * 1024];     // in-proj output (x_in | z)
__device__ float g_u [(size_t)M_TOT * DINNER];   // conv+silu output
__device__ float g_dbl[(size_t)M_TOT * 48];      // x_dbl: [dt_raw(16) | B(16) | C(16)]
__device__ float g_dt[(size_t)M_TOT * DINNER];   // softplus dt
__device__ float g_y [(size_t)M_TOT * DINNER];   // scan output (post gating)

// ============================================================
// K1: xz[m][j] = sum_c x[b][c][l] * W_in[j][c]
//     M=8192, N=1024, K=256. 128x128 tile, BK=8, 256 thr, 8x8/thread
// ============================================================
__global__ __launch_bounds__(256) void gemm_in(const float* __restrict__ x,
                                               const float* __restrict__ Win) {
    __shared__ float As[8][132];
    __shared__ float Bs[8][132];
    const int m0 = blockIdx.x * 128;
    const int n0 = blockIdx.y * 128;
    const int b  = m0 / SEQL;
    const int l0 = m0 % SEQL;
    const float* xb = x + (size_t)b * DMODEL * SEQL;
    const int tid = threadIdx.x;
    const int tx = tid & 15, ty = tid >> 4;

    float acc[8][8];
#pragma unroll
    for (int i = 0; i < 8; i++)
#pragma unroll
        for (int j = 0; j < 8; j++) acc[i][j] = 0.f;

    for (int k0 = 0; k0 < DMODEL; k0 += 8) {
        // A tile: As[kk][mm] = xb[(k0+kk)*L + l0+mm]   (coalesced over mm)
        {
            const int kk  = tid >> 5;          // 0..7
            const int mm4 = (tid & 31) * 4;    // 0..124
            float4 v = *(const float4*)&xb[(size_t)(k0 + kk) * SEQL + l0 + mm4];
            *(float4*)&As[kk][mm4] = v;
        }
        // B tile: Bs[kk][jj] = Win[(n0+jj)*256 + k0+kk]
        {
            const int jj  = tid & 127;
            const int kk4 = (tid >> 7) * 4;    // 0 or 4
            float4 v = *(const float4*)&Win[(size_t)(n0 + jj) * DMODEL + k0 + kk4];
            Bs[kk4 + 0][jj] = v.x; Bs[kk4 + 1][jj] = v.y;
            Bs[kk4 + 2][jj] = v.z; Bs[kk4 + 3][jj] = v.w;
        }
        __syncthreads();
#pragma unroll
        for (int kk = 0; kk < 8; kk++) {
            float ra[8], rb[8];
#pragma unroll
            for (int i = 0; i < 8; i++) ra[i] = As[kk][ty * 8 + i];
#pragma unroll
            for (int j = 0; j < 8; j++) rb[j] = Bs[kk][tx * 8 + j];
#pragma unroll
            for (int i = 0; i < 8; i++)
#pragma unroll
                for (int j = 0; j < 8; j++) acc[i][j] += ra[i] * rb[j];
        }
        __syncthreads();
    }
#pragma unroll
    for (int i = 0; i < 8; i++) {
        const size_t m = (size_t)(m0 + ty * 8 + i);
        float* dst = &g_xz[m * 1024 + n0 + tx * 8];
        *(float4*)&dst[0] = make_float4(acc[i][0], acc[i][1], acc[i][2], acc[i][3]);
        *(float4*)&dst[4] = make_float4(acc[i][4], acc[i][5], acc[i][6], acc[i][7]);
    }
}

// ============================================================
// K2: causal depthwise conv (d_conv=4) + bias + silu
// ============================================================
__global__ void conv_silu(const float* __restrict__ cw, const float* __restrict__ cb) {
    const int idx = blockIdx.x * blockDim.x + threadIdx.x; // over M_TOT*DINNER
    const int d = idx & (DINNER - 1);
    const int m = idx >> 9;
    const int l = m & (SEQL - 1);
    const float w0 = cw[d * 4 + 0], w1 = cw[d * 4 + 1];
    const float w2 = cw[d * 4 + 2], w3 = cw[d * 4 + 3];
    const float* base = &g_xz[(size_t)m * 1024 + d];
    float acc = cb[d] + base[0] * w3;                 // u[l] = sum_k x[l-3+k]*w[k]
    if (l >= 1) acc += base[-1024] * w2;
    if (l >= 2) acc += base[-2048] * w1;
    if (l >= 3) acc += base[-3072] * w0;
    const float sg = 1.f / (1.f + __expf(-acc));
    g_u[(size_t)m * DINNER + d] = acc * sg;
}

// ============================================================
// K3: x_dbl[m][0..47] = sum_d u[m][d]*W_x[j][d]
//     64 rows/block, 48 cols, 256 thr (16x16 -> 4 rows x 3 cols each), BK=16
// ============================================================
__global__ __launch_bounds__(256) void gemm_xdbl(const float* __restrict__ Wx) {
    __shared__ float Us[16][68];
    __shared__ float Ws[16][48];
    const int m0 = blockIdx.x * 64;
    const int tid = threadIdx.x;
    const int tx = tid & 15, ty = tid >> 4;

    float acc[4][3];
#pragma unroll
    for (int i = 0; i < 4; i++)
#pragma unroll
        for (int j = 0; j < 3; j++) acc[i][j] = 0.f;

    for (int k0 = 0; k0 < DINNER; k0 += 16) {
        {   // Us[kk][r] = u[(m0+r)*512 + k0+kk] ; 64x16 floats, transpose load
            const int r   = tid >> 2;
            const int kk4 = (tid & 3) * 4;
            float4 v = *(const float4*)&g_u[(size_t)(m0 + r) * DINNER + k0 + kk4];
            Us[kk4 + 0][r] = v.x; Us[kk4 + 1][r] = v.y;
            Us[kk4 + 2][r] = v.z; Us[kk4 + 3][r] = v.w;
        }
        if (tid < 192) { // Ws[kk][j] = Wx[j*512 + k0+kk] ; 48x16 floats
            const int j   = tid >> 2;
            const int kk4 = (tid & 3) * 4;
            float4 v = *(const float4*)&Wx[(size_t)j * DINNER + k0 + kk4];
            Ws[kk4 + 0][j] = v.x; Ws[kk4 + 1][j] = v.y;
            Ws[kk4 + 2][j] = v.z; Ws[kk4 + 3][j] = v.w;
        }
        __syncthreads();
#pragma unroll
        for (int kk = 0; kk < 16; kk++) {
            float ra[4], rb[3];
#pragma unroll
            for (int i = 0; i < 4; i++) ra[i] = Us[kk][ty * 4 + i];
#pragma unroll
            for (int j = 0; j < 3; j++) rb[j] = Ws[kk][tx * 3 + j];
#pragma unroll
            for (int i = 0; i < 4; i++)
#pragma unroll
                for (int j = 0; j < 3; j++) acc[i][j] += ra[i] * rb[j];
        }
        __syncthreads();
    }
#pragma unroll
    for (int i = 0; i < 4; i++) {
        const size_t m = (size_t)(m0 + ty * 4 + i);
#pragma unroll
        for (int j = 0; j < 3; j++) g_dbl[m * 48 + tx * 3 + j] = acc[i][j];
    }
}

// ============================================================
// K4: dt[m][d] = softplus( sum_r dt_raw[m][r]*W_dt[d][r] + b_dt[d] )
//     block = 256 threads (one m, half the d range); stage W_dt^T in shared
// ============================================================
__global__ __launch_bounds__(256) void dt_kernel(const float* __restrict__ Wdt,
                                                 const float* __restrict__ bdt) {
    __shared__ float r16[16];
    __shared__ float Ws[16][256];
    const int m  = blockIdx.x >> 1;
    const int d0 = (blockIdx.x & 1) << 8;
    const int tid = threadIdx.x;
    if (tid < 16) r16[tid] = g_dbl[(size_t)m * 48 + tid];
    // stage W_dt rows d0..d0+255 transposed: Ws[k][r] = Wdt[(d0+r)*16+k]
#pragma unroll
    for (int s = 0; s < 4; s++) {
        const int fidx = s * 256 + tid;      // over 1024 float4 loads
        const int r = fidx >> 2;
        const int c4 = (fidx & 3) * 4;
        float4 v = *(const float4*)&Wdt[(size_t)(d0 + r) * 16 + c4];
        Ws[c4 + 0][r] = v.x; Ws[c4 + 1][r] = v.y;
        Ws[c4 + 2][r] = v.z; Ws[c4 + 3][r] = v.w;
    }
    __syncthreads();
    const int d = d0 + tid;
    float acc = bdt[d];
#pragma unroll
    for (int k = 0; k < 16; k++) acc += r16[k] * Ws[k][tid];
    // stable softplus
    const float sp = fmaxf(acc, 0.f) + log1pf(__expf(-fabsf(acc)));
    g_dt[(size_t)m * DINNER + d] = sp;
}

// ============================================================
// K5: selective scan. warp handles 2 (b,d) chains; lane%16 = state index n.
//     h_n <- exp(dt*A_n)*h_n + dt*u*B_n ;  y = sum_n h_n*C_n (shfl reduce)
//     epilogue fused: y = (y + u*Dp) * silu(z)
// ============================================================
__global__ void scan_kernel(const float* __restrict__ A_log, const float* __restrict__ Dp) {
    const int gwarp = (blockIdx.x * blockDim.x + threadIdx.x) >> 5;
    const int lane  = threadIdx.x & 31;
    const int g     = lane & 15;                  // state index n
    const int chain = gwarp * 2 + (lane >> 4);    // 0..1023
    const int b = chain >> 9;
    const int d = chain & 511;
    const float A  = -__expf(A_log[d * 16 + g]);
    const float dp = Dp[d];
    float h = 0.f;
    const size_t mbase = (size_t)b * SEQL;
    for (int l = 0; l < SEQL; l++) {
        const size_t m = mbase + l;
        const float dt = g_dt[m * DINNER + d];
        const float u  = g_u [m * DINNER + d];
        const float Bv = g_dbl[m * 48 + 16 + g];
        const float Cv = g_dbl[m * 48 + 32 + g];
        h = __expf(dt * A) * h + (dt * u) * Bv;
        float p = h * Cv;
        p += __shfl_xor_sync(0xffffffffu, p, 8, 16);
        p += __shfl_xor_sync(0xffffffffu, p, 4, 16);
        p += __shfl_xor_sync(0xffffffffu, p, 2, 16);
        p += __shfl_xor_sync(0xffffffffu, p, 1, 16);
        if (g == 0) {
            const float z  = g_xz[m * 1024 + 512 + d];
            const float sg = 1.f / (1.f + __expf(-z));
            g_y[m * DINNER + d] = (p + u * dp) * (z * sg);
        }
    }
}

// ============================================================
// K6: out[b][c][l] = sum_d y[m][d]*W_out[c][d]
//     M=8192, N=256, K=512. 128x64 tile, BK=8, 256 thr, 8x4/thread
// ============================================================
__global__ __launch_bounds__(256) void gemm_out(const float* __restrict__ Wout,
                                                float* __restrict__ out) {
    __shared__ float As[8][132];
    __shared__ float Bs[8][68];
    const int m0 = blockIdx.x * 128;
    const int n0 = blockIdx.y * 64;
    const int tid = threadIdx.x;
    const int tx = tid & 15, ty = tid >> 4;

    float acc[8][4];
#pragma unroll
    for (int i = 0; i < 8; i++)
#pragma unroll
        for (int j = 0; j < 4; j++) acc[i][j] = 0.f;

    for (int k0 = 0; k0 < DINNER; k0 += 8) {
        {   // As[kk][mm] = y[(m0+mm)*512 + k0+kk]
            const int mm  = tid >> 1;
            const int kk4 = (tid & 1) * 4;
            float4 v = *(const float4*)&g_y[(size_t)(m0 + mm) * DINNER + k0 + kk4];
            As[kk4 + 0][mm] = v.x; As[kk4 + 1][mm] = v.y;
            As[kk4 + 2][mm] = v.z; As[kk4 + 3][mm] = v.w;
        }
        {   // Bs[kk][cc] = Wout[(n0+cc)*512 + k0+kk]
            const int cc  = tid & 63;
            const int kk2 = (tid >> 6) * 2;
            float2 v = *(const float2*)&Wout[(size_t)(n0 + cc) * DINNER + k0 + kk2];
            Bs[kk2 + 0][cc] = v.x; Bs[kk2 + 1][cc] = v.y;
        }
        __syncthreads();
#pragma unroll
        for (int kk = 0; kk < 8; kk++) {
            float ra[8], rb[4];
#pragma unroll
            for (int i = 0; i < 8; i++) ra[i] = As[kk][ty * 8 + i];
#pragma unroll
            for (int j = 0; j < 4; j++) rb[j] = Bs[kk][tx * 4 + j];
#pragma unroll
            for (int i = 0; i < 8; i++)
#pragma unroll
                for (int j = 0; j < 4; j++) acc[i][j] += ra[i] * rb[j];
        }
        __syncthreads();
    }
    const int b  = m0 / SEQL;
    const int l0 = m0 % SEQL;
#pragma unroll
    for (int j = 0; j < 4; j++) {
        const int c = n0 + tx * 4 + j;
        float* dst = out + ((size_t)b * DMODEL + c) * SEQL + l0 + ty * 8;
#pragma unroll
        for (int i = 0; i < 8; i++) dst[i] = acc[i][j];
    }
}

// ============================================================
extern "C" void kernel_launch(void* const* d_in, const int* in_sizes, int n_in,
                              void* d_out, int out_size) {
    const float* x    = (const float*)d_in[0];
    const float* Win  = (const float*)d_in[1];
    const float* cw   = (const float*)d_in[2];
    const float* cb   = (const float*)d_in[3];
    const float* Wx   = (const float*)d_in[4];
    const float* Wdt  = (const float*)d_in[5];
    const float* bdt  = (const float*)d_in[6];
    const float* Alog = (const float*)d_in[7];
    const float* Dp   = (const float*)d_in[8];
    const float* Wout = (const float*)d_in[9];
    float* out = (float*)d_out;

    dim3 g1(M_TOT / 128, 1024 / 128);
    gemm_in<<<g1, 256>>>(x, Win);
    conv_silu<<<(M_TOT * DINNER) / 256, 256>>>(cw, cb);
    gemm_xdbl<<<M_TOT / 64, 256>>>(Wx);
    dt_kernel<<<M_TOT * 2, 256>>>(Wdt, bdt);
    scan_kernel<<<128, 128>>>(Alog, Dp);
    dim3 g2(M_TOT / 128, DMODEL / 64);
    gemm_out<<<g2, 256>>>(Wout, out);
}

// round 2
// speedup vs baseline: 5.6279x; 5.6279x over previous
#include <cuda_runtime.h>
#include <math.h>

#define SEQL 4096
#define BATCH 2
#define DMODEL 256
#define DINNER 512
#define NSTATE 16
#define DTRANK 16
#define M_TOT (BATCH*SEQL)   // 8192
#define NCHAIN (BATCH*DINNER) // 1024
#define NCHUNK 64
#define CLEN   (SEQL/NCHUNK)  // 64

// -------- scratch (device globals; no dynamic allocation) --------
__device__ float g_xz[(size_t)M_TOT * 1024];     // in-proj output (x_in | z)
__device__ float g_u [(size_t)M_TOT * DINNER];   // conv+silu output
__device__ float g_dbl[(size_t)M_TOT * 48];      // x_dbl: [dt_raw(16) | B(16) | C(16)]
__device__ float g_dt[(size_t)M_TOT * DINNER];   // softplus dt
__device__ float g_y [(size_t)M_TOT * DINNER];   // scan output (post gating)
// chunked-scan state: [chunk][chain][state]
__device__ float g_P  [(size_t)NCHUNK * NCHAIN * NSTATE];
__device__ float g_hf [(size_t)NCHUNK * NCHAIN * NSTATE];
__device__ float g_hin[(size_t)NCHUNK * NCHAIN * NSTATE];

// ============================================================
// K1: xz[m][j] = sum_c x[b][c][l] * W_in[j][c]
//     M=8192, N=1024, K=256. 128x128 tile, BK=8, 256 thr, 8x8/thread
// ============================================================
__global__ __launch_bounds__(256) void gemm_in(const float* __restrict__ x,
                                               const float* __restrict__ Win) {
    __shared__ float As[8][132];
    __shared__ float Bs[8][132];
    const int m0 = blockIdx.x * 128;
    const int n0 = blockIdx.y * 128;
    const int b  = m0 / SEQL;
    const int l0 = m0 % SEQL;
    const float* xb = x + (size_t)b * DMODEL * SEQL;
    const int tid = threadIdx.x;
    const int tx = tid & 15, ty = tid >> 4;

    float acc[8][8];
#pragma unroll
    for (int i = 0; i < 8; i++)
#pragma unroll
        for (int j = 0; j < 8; j++) acc[i][j] = 0.f;

    for (int k0 = 0; k0 < DMODEL; k0 += 8) {
        {
            const int kk  = tid >> 5;
            const int mm4 = (tid & 31) * 4;
            float4 v = *(const float4*)&xb[(size_t)(k0 + kk) * SEQL + l0 + mm4];
            *(float4*)&As[kk][mm4] = v;
        }
        {
            const int jj  = tid & 127;
            const int kk4 = (tid >> 7) * 4;
            float4 v = *(const float4*)&Win[(size_t)(n0 + jj) * DMODEL + k0 + kk4];
            Bs[kk4 + 0][jj] = v.x; Bs[kk4 + 1][jj] = v.y;
            Bs[kk4 + 2][jj] = v.z; Bs[kk4 + 3][jj] = v.w;
        }
        __syncthreads();
#pragma unroll
        for (int kk = 0; kk < 8; kk++) {
            float ra[8], rb[8];
#pragma unroll
            for (int i = 0; i < 8; i++) ra[i] = As[kk][ty * 8 + i];
#pragma unroll
            for (int j = 0; j < 8; j++) rb[j] = Bs[kk][tx * 8 + j];
#pragma unroll
            for (int i = 0; i < 8; i++)
#pragma unroll
                for (int j = 0; j < 8; j++) acc[i][j] += ra[i] * rb[j];
        }
        __syncthreads();
    }
#pragma unroll
    for (int i = 0; i < 8; i++) {
        const size_t m = (size_t)(m0 + ty * 8 + i);
        float* dst = &g_xz[m * 1024 + n0 + tx * 8];
        *(float4*)&dst[0] = make_float4(acc[i][0], acc[i][1], acc[i][2], acc[i][3]);
        *(float4*)&dst[4] = make_float4(acc[i][4], acc[i][5], acc[i][6], acc[i][7]);
    }
}

// ============================================================
// K2: causal depthwise conv (d_conv=4) + bias + silu
// ============================================================
__global__ void conv_silu(const float* __restrict__ cw, const float* __restrict__ cb) {
    const int idx = blockIdx.x * blockDim.x + threadIdx.x;
    const int d = idx & (DINNER - 1);
    const int m = idx >> 9;
    const int l = m & (SEQL - 1);
    const float w0 = cw[d * 4 + 0], w1 = cw[d * 4 + 1];
    const float w2 = cw[d * 4 + 2], w3 = cw[d * 4 + 3];
    const float* base = &g_xz[(size_t)m * 1024 + d];
    float acc = cb[d] + base[0] * w3;
    if (l >= 1) acc += base[-1024] * w2;
    if (l >= 2) acc += base[-2048] * w1;
    if (l >= 3) acc += base[-3072] * w0;
    const float sg = 1.f / (1.f + __expf(-acc));
    g_u[(size_t)m * DINNER + d] = acc * sg;
}

// ============================================================
// K3: x_dbl[m][0..47] = sum_d u[m][d]*W_x[j][d]
// ============================================================
__global__ __launch_bounds__(256) void gemm_xdbl(const float* __restrict__ Wx) {
    __shared__ float Us[16][68];
    __shared__ float Ws[16][48];
    const int m0 = blockIdx.x * 64;
    const int tid = threadIdx.x;
    const int tx = tid & 15, ty = tid >> 4;

    float acc[4][3];
#pragma unroll
    for (int i = 0; i < 4; i++)
#pragma unroll
        for (int j = 0; j < 3; j++) acc[i][j] = 0.f;

    for (int k0 = 0; k0 < DINNER; k0 += 16) {
        {
            const int r   = tid >> 2;
            const int kk4 = (tid & 3) * 4;
            float4 v = *(const float4*)&g_u[(size_t)(m0 + r) * DINNER + k0 + kk4];
            Us[kk4 + 0][r] = v.x; Us[kk4 + 1][r] = v.y;
            Us[kk4 + 2][r] = v.z; Us[kk4 + 3][r] = v.w;
        }
        if (tid < 192) {
            const int j   = tid >> 2;
            const int kk4 = (tid & 3) * 4;
            float4 v = *(const float4*)&Wx[(size_t)j * DINNER + k0 + kk4];
            Ws[kk4 + 0][j] = v.x; Ws[kk4 + 1][j] = v.y;
            Ws[kk4 + 2][j] = v.z; Ws[kk4 + 3][j] = v.w;
        }
        __syncthreads();
#pragma unroll
        for (int kk = 0; kk < 16; kk++) {
            float ra[4], rb[3];
#pragma unroll
            for (int i = 0; i < 4; i++) ra[i] = Us[kk][ty * 4 + i];
#pragma unroll
            for (int j = 0; j < 3; j++) rb[j] = Ws[kk][tx * 3 + j];
#pragma unroll
            for (int i = 0; i < 4; i++)
#pragma unroll
                for (int j = 0; j < 3; j++) acc[i][j] += ra[i] * rb[j];
        }
        __syncthreads();
    }
#pragma unroll
    for (int i = 0; i < 4; i++) {
        const size_t m = (size_t)(m0 + ty * 4 + i);
#pragma unroll
        for (int j = 0; j < 3; j++) g_dbl[m * 48 + tx * 3 + j] = acc[i][j];
    }
}

// ============================================================
// K4: dt[m][d] = softplus( dt_raw[m] . W_dt[d] + b_dt[d] )
// block: 256 thr, 128 m-rows; each thread owns d=tid and d=tid+256
// (W_dt rows in registers), dt_raw tile staged once in shared.
// ============================================================
__global__ __launch_bounds__(256) void dt_kernel(const float* __restrict__ Wdt,
                                                 const float* __restrict__ bdt) {
    __shared__ float r[128][16];
    const int m0 = blockIdx.x * 128;
    const int tid = threadIdx.x;

    // stage dt_raw rows: 128x16 floats; thread t loads row t>>1, half (t&1)
    {
        const int row = tid >> 1;
        const int c4  = (tid & 1) * 8;
        float4 v0 = *(const float4*)&g_dbl[(size_t)(m0 + row) * 48 + c4];
        float4 v1 = *(const float4*)&g_dbl[(size_t)(m0 + row) * 48 + c4 + 4];
        *(float4*)&r[row][c4]     = v0;
        *(float4*)&r[row][c4 + 4] = v1;
    }
    const int d0 = tid, d1 = tid + 256;
    float w0[16], w1[16];
#pragma unroll
    for (int k = 0; k < 16; k++) { w0[k] = Wdt[d0 * 16 + k]; w1[k] = Wdt[d1 * 16 + k]; }
    const float b0 = bdt[d0], b1 = bdt[d1];
    __syncthreads();

    for (int mm = 0; mm < 128; mm++) {
        float a0 = b0, a1 = b1;
#pragma unroll
        for (int k = 0; k < 16; k++) {
            const float rv = r[mm][k];
            a0 += rv * w0[k];
            a1 += rv * w1[k];
        }
        const float s0 = fmaxf(a0, 0.f) + __logf(1.f + __expf(-fabsf(a0)));
        const float s1 = fmaxf(a1, 0.f) + __logf(1.f + __expf(-fabsf(a1)));
        const size_t m = (size_t)(m0 + mm);
        g_dt[m * DINNER + d0] = s0;
        g_dt[m * DINNER + d1] = s1;
    }
}

// ============================================================
// K5a: chunked scan pass 1 — per (chain, chunk): decay product P[n]
//      and local final state hf[n] (h0 = 0). Half-warp per worker.
// ============================================================
__global__ __launch_bounds__(128) void scan_p1(const float* __restrict__ A_log) {
    const int hw   = (blockIdx.x * blockDim.x + threadIdx.x) >> 4; // worker id
    const int g    = threadIdx.x & 15;
    const int chain = hw & (NCHAIN - 1);
    const int chunk = hw >> 10;
    const int b = chain >> 9;
    const int d = chain & (DINNER - 1);
    const float A = -__expf(A_log[d * 16 + g]);
    float h = 0.f, P = 1.f;
    const size_t mbase = (size_t)b * SEQL + chunk * CLEN;
#pragma unroll 4
    for (int i = 0; i < CLEN; i++) {
        const size_t m = mbase + i;
        const float dt = g_dt[m * DINNER + d];
        const float u  = g_u [m * DINNER + d];
        const float Bv = g_dbl[m * 48 + 16 + g];
        const float a  = __expf(dt * A);
        h = a * h + (dt * u) * Bv;
        P *= a;
    }
    const size_t o = ((size_t)chunk * NCHAIN + chain) * NSTATE + g;
    g_P [o] = P;
    g_hf[o] = h;
}

// ============================================================
// K5b: combine across chunks (serial over 64 chunks, parallel over
//      1024 chains x 16 states = 16384 threads)
// ============================================================
__global__ void scan_combine() {
    const int t = blockIdx.x * blockDim.x + threadIdx.x; // 0..16383
    float h = 0.f;
#pragma unroll 4
    for (int c = 0; c < NCHUNK; c++) {
        const size_t o = (size_t)c * (NCHAIN * NSTATE) + t;
        g_hin[o] = h;
        h = g_P[o] * h + g_hf[o];
    }
}

// ============================================================
// K5c: pass 3 — re-run each chunk from true h_in, emit gated y
// ============================================================
__global__ __launch_bounds__(128) void scan_p3(const float* __restrict__ A_log,
                                               const float* __restrict__ Dp) {
    const int hw   = (blockIdx.x * blockDim.x + threadIdx.x) >> 4;
    const int g    = threadIdx.x & 15;
    const int chain = hw & (NCHAIN - 1);
    const int chunk = hw >> 10;
    const int b = chain >> 9;
    const int d = chain & (DINNER - 1);
    const float A  = -__expf(A_log[d * 16 + g]);
    const float dp = Dp[d];
    float h = g_hin[((size_t)chunk * NCHAIN + chain) * NSTATE + g];
    const size_t mbase = (size_t)b * SEQL + chunk * CLEN;
    for (int i = 0; i < CLEN; i++) {
        const size_t m = mbase + i;
        const float dt = g_dt[m * DINNER + d];
        const float u  = g_u [m * DINNER + d];
        const float Bv = g_dbl[m * 48 + 16 + g];
        const float Cv = g_dbl[m * 48 + 32 + g];
        const float a  = __expf(dt * A);
        h = a * h + (dt * u) * Bv;
        float p = h * Cv;
        p += __shfl_xor_sync(0xffffffffu, p, 8, 16);
        p += __shfl_xor_sync(0xffffffffu, p, 4, 16);
        p += __shfl_xor_sync(0xffffffffu, p, 2, 16);
        p += __shfl_xor_sync(0xffffffffu, p, 1, 16);
        if (g == 0) {
            const float z  = g_xz[m * 1024 + 512 + d];
            const float sg = 1.f / (1.f + __expf(-z));
            g_y[m * DINNER + d] = (p + u * dp) * (z * sg);
        }
    }
}

// ============================================================
// K6: out[b][c][l] = sum_d y[m][d]*W_out[c][d]
// ============================================================
__global__ __launch_bounds__(256) void gemm_out(const float* __restrict__ Wout,
                                                float* __restrict__ out) {
    __shared__ float As[8][132];
    __shared__ float Bs[8][68];
    const int m0 = blockIdx.x * 128;
    const int n0 = blockIdx.y * 64;
    const int tid = threadIdx.x;
    const int tx = tid & 15, ty = tid >> 4;

    float acc[8][4];
#pragma unroll
    for (int i = 0; i < 8; i++)
#pragma unroll
        for (int j = 0; j < 4; j++) acc[i][j] = 0.f;

    for (int k0 = 0; k0 < DINNER; k0 += 8) {
        {
            const int mm  = tid >> 1;
            const int kk4 = (tid & 1) * 4;
            float4 v = *(const float4*)&g_y[(size_t)(m0 + mm) * DINNER + k0 + kk4];
            As[kk4 + 0][mm] = v.x; As[kk4 + 1][mm] = v.y;
            As[kk4 + 2][mm] = v.z; As[kk4 + 3][mm] = v.w;
        }
        {
            const int cc  = tid & 63;
            const int kk2 = (tid >> 6) * 2;
            float2 v = *(const float2*)&Wout[(size_t)(n0 + cc) * DINNER + k0 + kk2];
            Bs[kk2 + 0][cc] = v.x; Bs[kk2 + 1][cc] = v.y;
        }
        __syncthreads();
#pragma unroll
        for (int kk = 0; kk < 8; kk++) {
            float ra[8], rb[4];
#pragma unroll
            for (int i = 0; i < 8; i++) ra[i] = As[kk][ty * 8 + i];
#pragma unroll
            for (int j = 0; j < 4; j++) rb[j] = Bs[kk][tx * 4 + j];
#pragma unroll
            for (int i = 0; i < 8; i++)
#pragma unroll
                for (int j = 0; j < 4; j++) acc[i][j] += ra[i] * rb[j];
        }
        __syncthreads();
    }
    const int b  = m0 / SEQL;
    const int l0 = m0 % SEQL;
#pragma unroll
    for (int j = 0; j < 4; j++) {
        const int c = n0 + tx * 4 + j;
        float* dst = out + ((size_t)b * DMODEL + c) * SEQL + l0 + ty * 8;
#pragma unroll
        for (int i = 0; i < 8; i++) dst[i] = acc[i][j];
    }
}

// ============================================================
extern "C" void kernel_launch(void* const* d_in, const int* in_sizes, int n_in,
                              void* d_out, int out_size) {
    const float* x    = (const float*)d_in[0];
    const float* Win  = (const float*)d_in[1];
    const float* cw   = (const float*)d_in[2];
    const float* cb   = (const float*)d_in[3];
    const float* Wx   = (const float*)d_in[4];
    const float* Wdt  = (const float*)d_in[5];
    const float* bdt  = (const float*)d_in[6];
    const float* Alog = (const float*)d_in[7];
    const float* Dp   = (const float*)d_in[8];
    const float* Wout = (const float*)d_in[9];
    float* out = (float*)d_out;

    dim3 g1(M_TOT / 128, 1024 / 128);
    gemm_in<<<g1, 256>>>(x, Win);
    conv_silu<<<(M_TOT * DINNER) / 256, 256>>>(cw, cb);
    gemm_xdbl<<<M_TOT / 64, 256>>>(Wx);
    dt_kernel<<<M_TOT / 128, 256>>>(Wdt, bdt);

    // chunked selective scan: 64 chunks x 1024 chains, half-warp per worker
    const int workers = NCHUNK * NCHAIN;          // 65536
    const int blocks  = workers * 16 / 128;       // 8192
    scan_p1<<<blocks, 128>>>(Alog);
    scan_combine<<<64, 256>>>();
    scan_p3<<<blocks, 128>>>(Alog, Dp);

    dim3 g2(M_TOT / 128, DMODEL / 64);
    gemm_out<<<g2, 256>>>(Wout, out);
}